// round 9
// baseline (speedup 1.0000x reference)
#include <cuda_runtime.h>
#include <math.h>

#define BB   256
#define SS   196
#define RNN  1024
#define ATTH 512
#define KSPLIT 16
#define KCHUNK 64    // RNN / KSPLIT
#define SQ   49      // SS / 4

// Split-K partials for att_h = h @ w_h2att^T (bias folded in later).
__device__ float g_atth_part[KSPLIT * BB * ATTH];   // 8 MB
// Raw (pre-softmax) scores.
__device__ float g_scores[BB * SS];                 // 200 KB

// Fast accurate tanh: tanh(x) = 1 - 2/(exp(2x)+1); 2 MUFU, ~1e-7 abs err.
__device__ __forceinline__ float fast_tanhf(float x) {
  float e;
  asm("ex2.approx.f32 %0, %1;" : "=f"(e) : "f"(x * 2.885390081777927f));
  float r;
  asm("rcp.approx.f32 %0, %1;" : "=f"(r) : "f"(e + 1.0f));
  return fmaf(-2.0f, r, 1.0f);
}

// ---------------------------------------------------------------------------
// Kernel 1: split-K GEMM, 64x64x64 tiles, 4x4 microtile, f32x2 FMA.
//   att_h_part[z][m][n] = sum_{k in chunk z} h[m][k] * w[n][k]
// Grid: (ATTH/64, BB/64, KSPLIT) = (8, 4, 16) = 512 blocks, 256 threads.
// LDS traffic: 2 B/FMA (was 4) -> crossbar floor ~7.5 us chip-wide.
// ---------------------------------------------------------------------------
__global__ __launch_bounds__(256) void gemm_atth_kernel(
    const float* __restrict__ h, const float* __restrict__ w) {
  const int n0 = blockIdx.x * 64;
  const int m0 = blockIdx.y * 64;
  const int k0 = blockIdx.z * KCHUNK;

  // [k][m] transposed; pad 68 -> row stride 272 B (16-aligned, odd*16 banks).
  __shared__ float As[KCHUNK][68];
  __shared__ float Bs[KCHUNK][68];

  const int t  = threadIdx.x;        // 0..255
  const int r  = t >> 2;             // 0..63 (tile row)
  const int c0 = (t & 3) * 4;        // k sub-offset

  // Load full 64x64 A and B tiles, transposed into [k][m].
#pragma unroll
  for (int i = 0; i < 4; i++) {
    const int c = c0 + i * 16;
    const float4 v = *(const float4*)(h + (size_t)(m0 + r) * RNN + k0 + c);
    As[c + 0][r] = v.x; As[c + 1][r] = v.y; As[c + 2][r] = v.z; As[c + 3][r] = v.w;
  }
#pragma unroll
  for (int i = 0; i < 4; i++) {
    const int c = c0 + i * 16;
    const float4 v = *(const float4*)(w + (size_t)(n0 + r) * RNN + k0 + c);
    Bs[c + 0][r] = v.x; Bs[c + 1][r] = v.y; Bs[c + 2][r] = v.z; Bs[c + 3][r] = v.w;
  }
  __syncthreads();

  const int tx = (t & 15) * 4;       // n micro (4 cols)
  const int ty = (t >> 4) * 4;       // m micro (4 rows)

  // acc[j*2+p]: output col (tx+j), packed rows (ty+2p, ty+2p+1).
  unsigned long long acc[8] = {0ull, 0ull, 0ull, 0ull, 0ull, 0ull, 0ull, 0ull};

#pragma unroll 8
  for (int k = 0; k < KCHUNK; k++) {
    const unsigned long long a0 = *(const unsigned long long*)&As[k][ty];
    const unsigned long long a1 = *(const unsigned long long*)&As[k][ty + 2];
    const float4 b = *(const float4*)&Bs[k][tx];
    const float bs[4] = {b.x, b.y, b.z, b.w};
#pragma unroll
    for (int j = 0; j < 4; j++) {
      unsigned long long bb;
      asm("mov.b64 %0, {%1, %1};" : "=l"(bb) : "r"(__float_as_uint(bs[j])));
      asm("fma.rn.f32x2 %0, %1, %2, %0;" : "+l"(acc[j * 2 + 0]) : "l"(a0), "l"(bb));
      asm("fma.rn.f32x2 %0, %1, %2, %0;" : "+l"(acc[j * 2 + 1]) : "l"(a1), "l"(bb));
    }
  }

  // Unpack and store 4x4 block (4 x float4, 16B aligned).
  float* dst = g_atth_part + (size_t)blockIdx.z * BB * ATTH;
#pragma unroll
  for (int i = 0; i < 4; i++) {
    const int p = i >> 1, hi = i & 1;
    float4 o;
    o.x = __uint_as_float(hi ? (unsigned)(acc[0 * 2 + p] >> 32) : (unsigned)acc[0 * 2 + p]);
    o.y = __uint_as_float(hi ? (unsigned)(acc[1 * 2 + p] >> 32) : (unsigned)acc[1 * 2 + p]);
    o.z = __uint_as_float(hi ? (unsigned)(acc[2 * 2 + p] >> 32) : (unsigned)acc[2 * 2 + p]);
    o.w = __uint_as_float(hi ? (unsigned)(acc[3 * 2 + p] >> 32) : (unsigned)acc[3 * 2 + p]);
    *(float4*)(dst + (size_t)(m0 + ty + i) * ATTH + n0 + tx) = o;
  }
}

// ---------------------------------------------------------------------------
// Kernel 2: raw scores.
//   scores[b,s] = sum_a tanh(p_att[b,s,a] + att_h[b,a] + bias[a]) * w_alpha[a]
// Grid: (BB, 4) = 1024 blocks, 256 threads. Block (b,q) handles 49 s-rows.
// ---------------------------------------------------------------------------
__global__ __launch_bounds__(256) void scores_kernel(
    const float* __restrict__ p_att,
    const float* __restrict__ b_h2att,
    const float* __restrict__ w_alpha) {
  __shared__ __align__(16) float sh_atth[ATTH];
  __shared__ __align__(16) float sh_wa[ATTH];

  const int b    = blockIdx.x;
  const int q    = blockIdx.y;
  const int tid  = threadIdx.x;
  const int warp = tid >> 5;
  const int lane = tid & 31;

#pragma unroll
  for (int a = tid; a < ATTH; a += 256) {
    float v = b_h2att[a];
#pragma unroll
    for (int z = 0; z < KSPLIT; z++)
      v += g_atth_part[(size_t)z * BB * ATTH + (size_t)b * ATTH + a];
    sh_atth[a] = v;
    sh_wa[a] = w_alpha[a];
  }
  __syncthreads();

  const float* pbase = p_att + (size_t)b * SS * ATTH + (size_t)q * SQ * ATTH;
  for (int sl = warp; sl < SQ; sl += 8) {
    const float* row = pbase + (size_t)sl * ATTH;
    float acc = 0.f;
#pragma unroll
    for (int i = 0; i < 4; i++) {
      const int a = i * 128 + lane * 4;
      const float4 p  = *(const float4*)(row + a);
      const float4 ah = *(const float4*)(sh_atth + a);
      const float4 wa = *(const float4*)(sh_wa + a);
      acc = fmaf(fast_tanhf(p.x + ah.x), wa.x, acc);
      acc = fmaf(fast_tanhf(p.y + ah.y), wa.y, acc);
      acc = fmaf(fast_tanhf(p.z + ah.z), wa.z, acc);
      acc = fmaf(fast_tanhf(p.w + ah.w), wa.w, acc);
    }
#pragma unroll
    for (int off = 16; off > 0; off >>= 1)
      acc += __shfl_xor_sync(0xffffffffu, acc, off);
    if (lane == 0) g_scores[(size_t)b * SS + q * SQ + sl] = acc;
  }
}

// ---------------------------------------------------------------------------
// Kernel 3: redundant softmax prologue + weighted sum, direct store.
//   out[b, q*256+t] = sum_s softmax(scores[b])[s] * att_feats[b,s,q*256+t]
// Grid: (BB, 4) = 1024 blocks, 256 threads, 1 output dim per thread.
// ---------------------------------------------------------------------------
__global__ __launch_bounds__(256) void wsum_kernel(
    const float* __restrict__ att_feats,
    float* __restrict__ out) {
  __shared__ float sh_w[SS];
  __shared__ float red[8];

  const int b    = blockIdx.x;
  const int q    = blockIdx.y;
  const int tid  = threadIdx.x;
  const int warp = tid >> 5;
  const int lane = tid & 31;

  // --- softmax over 196 scores ---
  const float v = (tid < SS) ? g_scores[(size_t)b * SS + tid] : -INFINITY;

  float m = v;
#pragma unroll
  for (int off = 16; off > 0; off >>= 1)
    m = fmaxf(m, __shfl_xor_sync(0xffffffffu, m, off));
  if (lane == 0) red[warp] = m;
  __syncthreads();
  m = red[0];
#pragma unroll
  for (int i = 1; i < 8; i++) m = fmaxf(m, red[i]);
  __syncthreads();

  const float e = (tid < SS) ? __expf(v - m) : 0.f;
  float sum = e;
#pragma unroll
  for (int off = 16; off > 0; off >>= 1)
    sum += __shfl_xor_sync(0xffffffffu, sum, off);
  if (lane == 0) red[warp] = sum;
  __syncthreads();
  float tot = red[0];
#pragma unroll
  for (int i = 1; i < 8; i++) tot += red[i];
  const float inv = 1.f / tot;
  if (tid < SS) sh_w[tid] = e * inv;
  __syncthreads();

  // --- stream att_feats: 196 coalesced scalar loads per thread ---
  const int d = q * 256 + tid;
  const float* ab = att_feats + (size_t)b * SS * RNN + d;
  float acc = 0.f;
#pragma unroll 4
  for (int s = 0; s < SS; s++)
    acc = fmaf(sh_w[s], ab[(size_t)s * RNN], acc);

  out[(size_t)b * RNN + d] = acc;
}

// ---------------------------------------------------------------------------
// Launch. Inputs: h, att_feats, p_att_feats, w_h2att, b_h2att, w_alpha,
// b_alpha (unused: softmax shift-invariant).
// ---------------------------------------------------------------------------
extern "C" void kernel_launch(void* const* d_in, const int* in_sizes, int n_in,
                              void* d_out, int out_size) {
  (void)in_sizes; (void)n_in; (void)out_size;
  const float* h         = (const float*)d_in[0];
  const float* att_feats = (const float*)d_in[1];
  const float* p_att     = (const float*)d_in[2];
  const float* w_h2att   = (const float*)d_in[3];
  const float* b_h2att   = (const float*)d_in[4];
  const float* w_alpha   = (const float*)d_in[5];
  float* out = (float*)d_out;

  dim3 g1(ATTH / 64, BB / 64, KSPLIT);      // 512 blocks
  gemm_atth_kernel<<<g1, 256>>>(h, w_h2att);
  scores_kernel<<<dim3(BB, 4), 256>>>(p_att, b_h2att, w_alpha);
  wsum_kernel<<<dim3(BB, 4), 256>>>(att_feats, out);
}

// round 10
// speedup vs baseline: 1.2129x; 1.2129x over previous
#include <cuda_runtime.h>
#include <math.h>

#define BB   256
#define SS   196
#define RNN  1024
#define ATTH 512
#define KSPLIT 16
#define KCHUNK 64    // RNN / KSPLIT
#define SQ   49      // SS / 4

// Split-K partials for att_h = h @ w_h2att^T (bias folded in later).
__device__ float g_atth_part[KSPLIT * BB * ATTH];   // 8 MB
// Raw (pre-softmax) scores.
__device__ float g_scores[BB * SS];                 // 200 KB

// Fast accurate tanh: tanh(x) = 1 - 2/(exp(2x)+1); 2 MUFU, ~1e-7 abs err.
__device__ __forceinline__ float fast_tanhf(float x) {
  float e;
  asm("ex2.approx.f32 %0, %1;" : "=f"(e) : "f"(x * 2.885390081777927f));
  float r;
  asm("rcp.approx.f32 %0, %1;" : "=f"(r) : "f"(e + 1.0f));
  return fmaf(-2.0f, r, 1.0f);
}

// ---------------------------------------------------------------------------
// Kernel 1: split-K GEMM, 32(m) x 64(n) x 64(k) tiles, broadcast microtile.
//   Warp w owns m-rows [4w, 4w+4) for ALL 64 n-cols: the A-side LDS.128 is
//   warp-uniform (broadcast, ~free); B-side is a conflict-free float2/lane.
//   LDS crossbar ~1.5 B/FMA -> chip floor ~5.6 us.
// Grid: (ATTH/64, BB/32, KSPLIT) = (8, 8, 16) = 1024 blocks, 256 threads.
// ---------------------------------------------------------------------------
__global__ __launch_bounds__(256) void gemm_atth_kernel(
    const float* __restrict__ h, const float* __restrict__ w) {
  const int n0 = blockIdx.x * 64;
  const int m0 = blockIdx.y * 32;
  const int k0 = blockIdx.z * KCHUNK;

  __shared__ float As[KCHUNK][36];   // [k][m], row 144B (16B-aligned)
  __shared__ float Bs[KCHUNK][66];   // [k][n], row 264B (8B-aligned)

  const int t = threadIdx.x;         // 0..255

  // Load A tile (32 x 64) transposed into [k][m]: 8 floats per thread.
  {
    const int r  = t >> 3;           // 0..31
    const int c0 = (t & 7) * 8;      // k offset
    const float4 v0 = *(const float4*)(h + (size_t)(m0 + r) * RNN + k0 + c0);
    const float4 v1 = *(const float4*)(h + (size_t)(m0 + r) * RNN + k0 + c0 + 4);
    As[c0 + 0][r] = v0.x; As[c0 + 1][r] = v0.y; As[c0 + 2][r] = v0.z; As[c0 + 3][r] = v0.w;
    As[c0 + 4][r] = v1.x; As[c0 + 5][r] = v1.y; As[c0 + 6][r] = v1.z; As[c0 + 7][r] = v1.w;
  }
  // Load B tile (64 x 64) transposed into [k][n]: 16 floats per thread.
  {
    const int r  = t >> 2;           // 0..63
    const int c0 = (t & 3) * 4;      // k offset base
#pragma unroll
    for (int i = 0; i < 4; i++) {
      const int c = c0 + i * 16;
      const float4 v = *(const float4*)(w + (size_t)(n0 + r) * RNN + k0 + c);
      Bs[c + 0][r] = v.x; Bs[c + 1][r] = v.y; Bs[c + 2][r] = v.z; Bs[c + 3][r] = v.w;
    }
  }
  __syncthreads();

  const int warp = t >> 5;           // 0..7 -> m rows 4*warp..4*warp+3
  const int lane = t & 31;           // n cols 2*lane, 2*lane+1
  const int w4   = warp * 4;
  const int l2   = lane * 2;

  // acc[j][p]: col (n0+l2+j), packed m-rows (w4+2p, w4+2p+1).
  unsigned long long acc[2][2] = {{0ull, 0ull}, {0ull, 0ull}};

#pragma unroll 8
  for (int k = 0; k < KCHUNK; k++) {
    const float4 a = *(const float4*)&As[k][w4];        // broadcast LDS.128
    const float2 b = *(const float2*)&Bs[k][l2];        // conflict-free LDS.64
    unsigned long long a01, a23, b0, b1;
    asm("mov.b64 %0, {%1, %2};" : "=l"(a01) : "r"(__float_as_uint(a.x)), "r"(__float_as_uint(a.y)));
    asm("mov.b64 %0, {%1, %2};" : "=l"(a23) : "r"(__float_as_uint(a.z)), "r"(__float_as_uint(a.w)));
    asm("mov.b64 %0, {%1, %1};" : "=l"(b0) : "r"(__float_as_uint(b.x)));
    asm("mov.b64 %0, {%1, %1};" : "=l"(b1) : "r"(__float_as_uint(b.y)));
    asm("fma.rn.f32x2 %0, %1, %2, %0;" : "+l"(acc[0][0]) : "l"(a01), "l"(b0));
    asm("fma.rn.f32x2 %0, %1, %2, %0;" : "+l"(acc[0][1]) : "l"(a23), "l"(b0));
    asm("fma.rn.f32x2 %0, %1, %2, %0;" : "+l"(acc[1][0]) : "l"(a01), "l"(b1));
    asm("fma.rn.f32x2 %0, %1, %2, %0;" : "+l"(acc[1][1]) : "l"(a23), "l"(b1));
  }

  // Store 4 rows x 2 cols; lanes cover 64 consecutive n -> coalesced float2.
  float* dst = g_atth_part + (size_t)blockIdx.z * BB * ATTH;
#pragma unroll
  for (int i = 0; i < 4; i++) {
    const int p = i >> 1, hi = i & 1;
    float2 o;
    o.x = __uint_as_float(hi ? (unsigned)(acc[0][p] >> 32) : (unsigned)acc[0][p]);
    o.y = __uint_as_float(hi ? (unsigned)(acc[1][p] >> 32) : (unsigned)acc[1][p]);
    *(float2*)(dst + (size_t)(m0 + w4 + i) * ATTH + n0 + l2) = o;
  }
}

// ---------------------------------------------------------------------------
// Kernel 2: raw scores.
//   scores[b,s] = sum_a tanh(p_att[b,s,a] + att_h[b,a] + bias[a]) * w_alpha[a]
// Grid: (BB, 4) = 1024 blocks, 256 threads. Block (b,q) handles 49 s-rows.
// ---------------------------------------------------------------------------
__global__ __launch_bounds__(256) void scores_kernel(
    const float* __restrict__ p_att,
    const float* __restrict__ b_h2att,
    const float* __restrict__ w_alpha) {
  __shared__ __align__(16) float sh_atth[ATTH];
  __shared__ __align__(16) float sh_wa[ATTH];

  const int b    = blockIdx.x;
  const int q    = blockIdx.y;
  const int tid  = threadIdx.x;
  const int warp = tid >> 5;
  const int lane = tid & 31;

#pragma unroll
  for (int a = tid; a < ATTH; a += 256) {
    float v = b_h2att[a];
#pragma unroll
    for (int z = 0; z < KSPLIT; z++)
      v += g_atth_part[(size_t)z * BB * ATTH + (size_t)b * ATTH + a];
    sh_atth[a] = v;
    sh_wa[a] = w_alpha[a];
  }
  __syncthreads();

  const float* pbase = p_att + (size_t)b * SS * ATTH + (size_t)q * SQ * ATTH;
  for (int sl = warp; sl < SQ; sl += 8) {
    const float* row = pbase + (size_t)sl * ATTH;
    float acc = 0.f;
#pragma unroll
    for (int i = 0; i < 4; i++) {
      const int a = i * 128 + lane * 4;
      const float4 p  = *(const float4*)(row + a);
      const float4 ah = *(const float4*)(sh_atth + a);
      const float4 wa = *(const float4*)(sh_wa + a);
      acc = fmaf(fast_tanhf(p.x + ah.x), wa.x, acc);
      acc = fmaf(fast_tanhf(p.y + ah.y), wa.y, acc);
      acc = fmaf(fast_tanhf(p.z + ah.z), wa.z, acc);
      acc = fmaf(fast_tanhf(p.w + ah.w), wa.w, acc);
    }
#pragma unroll
    for (int off = 16; off > 0; off >>= 1)
      acc += __shfl_xor_sync(0xffffffffu, acc, off);
    if (lane == 0) g_scores[(size_t)b * SS + q * SQ + sl] = acc;
  }
}

// ---------------------------------------------------------------------------
// Kernel 3: redundant softmax prologue + weighted sum, direct store.
//   out[b, q*256+t] = sum_s softmax(scores[b])[s] * att_feats[b,s,q*256+t]
// Grid: (BB, 4) = 1024 blocks, 256 threads, 1 output dim per thread.
// ---------------------------------------------------------------------------
__global__ __launch_bounds__(256) void wsum_kernel(
    const float* __restrict__ att_feats,
    float* __restrict__ out) {
  __shared__ float sh_w[SS];
  __shared__ float red[8];

  const int b    = blockIdx.x;
  const int q    = blockIdx.y;
  const int tid  = threadIdx.x;
  const int warp = tid >> 5;
  const int lane = tid & 31;

  // --- softmax over 196 scores ---
  const float v = (tid < SS) ? g_scores[(size_t)b * SS + tid] : -INFINITY;

  float m = v;
#pragma unroll
  for (int off = 16; off > 0; off >>= 1)
    m = fmaxf(m, __shfl_xor_sync(0xffffffffu, m, off));
  if (lane == 0) red[warp] = m;
  __syncthreads();
  m = red[0];
#pragma unroll
  for (int i = 1; i < 8; i++) m = fmaxf(m, red[i]);
  __syncthreads();

  const float e = (tid < SS) ? __expf(v - m) : 0.f;
  float sum = e;
#pragma unroll
  for (int off = 16; off > 0; off >>= 1)
    sum += __shfl_xor_sync(0xffffffffu, sum, off);
  if (lane == 0) red[warp] = sum;
  __syncthreads();
  float tot = red[0];
#pragma unroll
  for (int i = 1; i < 8; i++) tot += red[i];
  const float inv = 1.f / tot;
  if (tid < SS) sh_w[tid] = e * inv;
  __syncthreads();

  // --- stream att_feats: 196 coalesced scalar loads per thread ---
  const int d = q * 256 + tid;
  const float* ab = att_feats + (size_t)b * SS * RNN + d;
  float acc = 0.f;
#pragma unroll 4
  for (int s = 0; s < SS; s++)
    acc = fmaf(sh_w[s], ab[(size_t)s * RNN], acc);

  out[(size_t)b * RNN + d] = acc;
}

// ---------------------------------------------------------------------------
// Launch. Inputs: h, att_feats, p_att_feats, w_h2att, b_h2att, w_alpha,
// b_alpha (unused: softmax shift-invariant).
// ---------------------------------------------------------------------------
extern "C" void kernel_launch(void* const* d_in, const int* in_sizes, int n_in,
                              void* d_out, int out_size) {
  (void)in_sizes; (void)n_in; (void)out_size;
  const float* h         = (const float*)d_in[0];
  const float* att_feats = (const float*)d_in[1];
  const float* p_att     = (const float*)d_in[2];
  const float* w_h2att   = (const float*)d_in[3];
  const float* b_h2att   = (const float*)d_in[4];
  const float* w_alpha   = (const float*)d_in[5];
  float* out = (float*)d_out;

  dim3 g1(ATTH / 64, BB / 32, KSPLIT);      // (8, 8, 16) = 1024 blocks
  gemm_atth_kernel<<<g1, 256>>>(h, w_h2att);
  scores_kernel<<<dim3(BB, 4), 256>>>(p_att, b_h2att, w_alpha);
  wsum_kernel<<<dim3(BB, 4), 256>>>(att_feats, out);
}